// round 1
// baseline (speedup 1.0000x reference)
#include <cuda_runtime.h>
#include <math.h>

#define BATCH 512
#define INDIM 256
#define HIDD  512
#define HID2  256
#define PAT   10

// -------- scratch (no allocations allowed) --------
__device__ float g_H [BATCH * HIDD];
__device__ float g_H2[BATCH * HID2];
__device__ float g_A [BATCH * HIDD];
__device__ float g_C [BATCH * HIDD];

// ============================================================
// Generic fp32 GEMM: Out[m][n] = sum_k X[m][k] * W[n][k]  (+epilogue)
// 64x64 block tile, 16-deep K chunks, 256 threads, 4x4 micro-tile.
// MODE 0: BN(+b1)+ReLU   (p0=b1, p1=gamma, p2=beta, p3=mean, p4=var)
// MODE 1: plain
// MODE 2: + p0[n]
// MODE 3: relu(v + p0[n])
// ============================================================
template <int MODE>
__global__ __launch_bounds__(256)
void gemm64(const float* __restrict__ X, const float* __restrict__ W,
            float* __restrict__ Out, int N, int K,
            const float* __restrict__ p0, const float* __restrict__ p1,
            const float* __restrict__ p2, const float* __restrict__ p3,
            const float* __restrict__ p4)
{
    __shared__ float Xs[16][64];
    __shared__ float Wt[16][64];

    const int t   = threadIdx.x;
    const int txn = t & 15;       // 0..15  (n dim)
    const int tym = t >> 4;       // 0..15  (m dim)
    const int m0  = blockIdx.y * 64;
    const int n0  = blockIdx.x * 64;

    const int lr = t >> 2;            // 0..63 row within tile
    const int lc = (t & 3) << 2;      // k offset 0,4,8,12

    float acc[4][4];
#pragma unroll
    for (int r = 0; r < 4; r++)
#pragma unroll
        for (int c = 0; c < 4; c++) acc[r][c] = 0.f;

    for (int k0 = 0; k0 < K; k0 += 16) {
        float4 xv = *(const float4*)(X + (size_t)(m0 + lr) * K + k0 + lc);
        float4 wv = *(const float4*)(W + (size_t)(n0 + lr) * K + k0 + lc);
        Xs[lc + 0][lr] = xv.x; Xs[lc + 1][lr] = xv.y;
        Xs[lc + 2][lr] = xv.z; Xs[lc + 3][lr] = xv.w;
        Wt[lc + 0][lr] = wv.x; Wt[lc + 1][lr] = wv.y;
        Wt[lc + 2][lr] = wv.z; Wt[lc + 3][lr] = wv.w;
        __syncthreads();
#pragma unroll
        for (int kk = 0; kk < 16; kk++) {
            float4 a = *(const float4*)&Xs[kk][tym << 2];
            float4 b = *(const float4*)&Wt[kk][txn << 2];
            acc[0][0] += a.x * b.x; acc[0][1] += a.x * b.y;
            acc[0][2] += a.x * b.z; acc[0][3] += a.x * b.w;
            acc[1][0] += a.y * b.x; acc[1][1] += a.y * b.y;
            acc[1][2] += a.y * b.z; acc[1][3] += a.y * b.w;
            acc[2][0] += a.z * b.x; acc[2][1] += a.z * b.y;
            acc[2][2] += a.z * b.z; acc[2][3] += a.z * b.w;
            acc[3][0] += a.w * b.x; acc[3][1] += a.w * b.y;
            acc[3][2] += a.w * b.z; acc[3][3] += a.w * b.w;
        }
        __syncthreads();
    }

#pragma unroll
    for (int r = 0; r < 4; r++) {
        const int m  = m0 + (tym << 2) + r;
        const int nb = n0 + (txn << 2);
        float vals[4];
#pragma unroll
        for (int c = 0; c < 4; c++) {
            const int n = nb + c;
            float v = acc[r][c];
            if (MODE == 0) {
                v += p0[n];
                v = p1[n] * (v - p3[n]) * rsqrtf(p4[n] + 1e-5f) + p2[n];
                v = fmaxf(v, 0.f);
            } else if (MODE == 2) {
                v += p0[n];
            } else if (MODE == 3) {
                v = fmaxf(v + p0[n], 0.f);
            }
            vals[c] = v;
        }
        float4 o = make_float4(vals[0], vals[1], vals[2], vals[3]);
        *(float4*)(Out + (size_t)m * N + nb) = o;
    }
}

// ============================================================
// scores + softmax: one warp per batch row.
// scores[i][p] = dot(H2[i], W3[p]) + b3[p]; probs = softmax(scores)
// ============================================================
__global__ __launch_bounds__(128)
void scores_kernel(const float* __restrict__ H2, const float* __restrict__ W3,
                   const float* __restrict__ b3,
                   float* __restrict__ out_probs, float* __restrict__ out_scores)
{
    const int warp = threadIdx.x >> 5;
    const int lane = threadIdx.x & 31;
    const int row  = blockIdx.x * 4 + warp;
    const float* h = H2 + (size_t)row * HID2;

    float acc[PAT];
#pragma unroll
    for (int p = 0; p < PAT; p++) acc[p] = 0.f;

    for (int k = lane; k < HID2; k += 32) {
        float hv = h[k];
#pragma unroll
        for (int p = 0; p < PAT; p++) acc[p] += hv * W3[p * HID2 + k];
    }
#pragma unroll
    for (int p = 0; p < PAT; p++) {
#pragma unroll
        for (int off = 16; off; off >>= 1)
            acc[p] += __shfl_xor_sync(0xFFFFFFFFu, acc[p], off);
    }
    if (lane == 0) {
        float s[PAT];
        float mx = -1e30f;
#pragma unroll
        for (int p = 0; p < PAT; p++) { s[p] = acc[p] + b3[p]; mx = fmaxf(mx, s[p]); }
        float sum = 0.f;
        float e[PAT];
#pragma unroll
        for (int p = 0; p < PAT; p++) { e[p] = expf(s[p] - mx); sum += e[p]; }
        float inv = 1.f / sum;
#pragma unroll
        for (int p = 0; p < PAT; p++) {
            out_scores[row * PAT + p] = s[p];
            out_probs [row * PAT + p] = e[p] * inv;
        }
    }
}

// ============================================================
// Pairwise similarity.
// logit(i,j) = sum_k relu(A[i,k] + C'[j,k]) * w[k] + bs2   (C' has bs1 folded)
// Output: out[i][j] = out[j][i] = sigmoid(logit(i,j)) for i<j, 0 on diagonal.
// 32x32 pair tiles, only upper-triangle blocks do work.
// ============================================================
__global__ __launch_bounds__(256)
void sim_kernel(const float* __restrict__ A, const float* __restrict__ Cp,
                const float* __restrict__ w, const float* __restrict__ bs2p,
                float* __restrict__ out)
{
    const int bi = blockIdx.y, bj = blockIdx.x;
    if (bj < bi) return;

    __shared__ float As[32][33];
    __shared__ float Cs[32][33];
    __shared__ float Wsh[32];

    const int t  = threadIdx.x;
    const int tx = t & 15;   // j dim
    const int ty = t >> 4;   // i dim
    const int i0 = bi * 32, j0 = bj * 32;

    const int lr  = t >> 3;           // 0..31
    const int lc4 = (t & 7) << 2;     // 0,4,...,28

    float acc00 = 0.f, acc01 = 0.f, acc10 = 0.f, acc11 = 0.f;

    for (int k0 = 0; k0 < HIDD; k0 += 32) {
        float4 av = *(const float4*)(A  + (size_t)(i0 + lr) * HIDD + k0 + lc4);
        float4 cv = *(const float4*)(Cp + (size_t)(j0 + lr) * HIDD + k0 + lc4);
        As[lr][lc4 + 0] = av.x; As[lr][lc4 + 1] = av.y;
        As[lr][lc4 + 2] = av.z; As[lr][lc4 + 3] = av.w;
        Cs[lr][lc4 + 0] = cv.x; Cs[lr][lc4 + 1] = cv.y;
        Cs[lr][lc4 + 2] = cv.z; Cs[lr][lc4 + 3] = cv.w;
        if (t < 32) Wsh[t] = w[k0 + t];
        __syncthreads();
#pragma unroll
        for (int kk = 0; kk < 32; kk++) {
            const float wv = Wsh[kk];
            const float a0 = As[(ty << 1) + 0][kk];
            const float a1 = As[(ty << 1) + 1][kk];
            const float c0 = Cs[(tx << 1) + 0][kk];
            const float c1 = Cs[(tx << 1) + 1][kk];
            acc00 += fmaxf(a0 + c0, 0.f) * wv;
            acc01 += fmaxf(a0 + c1, 0.f) * wv;
            acc10 += fmaxf(a1 + c0, 0.f) * wv;
            acc11 += fmaxf(a1 + c1, 0.f) * wv;
        }
        __syncthreads();
    }

    const float bs2 = *bs2p;
    float accs[2][2] = {{acc00, acc01}, {acc10, acc11}};
#pragma unroll
    for (int r = 0; r < 2; r++) {
#pragma unroll
        for (int c = 0; c < 2; c++) {
            const int i = i0 + (ty << 1) + r;
            const int j = j0 + (tx << 1) + c;
            if (i < j) {
                const float s = 1.f / (1.f + expf(-(accs[r][c] + bs2)));
                out[(size_t)i * BATCH + j] = s;
                out[(size_t)j * BATCH + i] = s;
            } else if (i == j) {
                out[(size_t)i * BATCH + j] = 0.f;
            }
        }
    }
}

// ============================================================
extern "C" void kernel_launch(void* const* d_in, const int* in_sizes, int n_in,
                              void* d_out, int out_size)
{
    const float* x     = (const float*)d_in[0];
    const float* W1    = (const float*)d_in[1];
    const float* b1    = (const float*)d_in[2];
    const float* gam   = (const float*)d_in[3];
    const float* bet   = (const float*)d_in[4];
    const float* mean  = (const float*)d_in[5];
    const float* var   = (const float*)d_in[6];
    const float* W2    = (const float*)d_in[7];
    const float* b2    = (const float*)d_in[8];
    const float* W3    = (const float*)d_in[9];
    const float* b3    = (const float*)d_in[10];
    const float* Wa    = (const float*)d_in[11];
    const float* Wb    = (const float*)d_in[12];
    const float* bs1   = (const float*)d_in[13];
    const float* ws2   = (const float*)d_in[14];
    const float* bs2   = (const float*)d_in[15];

    float* out        = (float*)d_out;
    float* out_probs  = out;
    float* out_scores = out + BATCH * PAT;
    float* out_sim    = out + 2 * BATCH * PAT;

    float *H, *H2, *A, *C;
    cudaGetSymbolAddress((void**)&H,  g_H);
    cudaGetSymbolAddress((void**)&H2, g_H2);
    cudaGetSymbolAddress((void**)&A,  g_A);
    cudaGetSymbolAddress((void**)&C,  g_C);

    // 1) H = relu(BN(x @ W1^T + b1))          [512,512]
    gemm64<0><<<dim3(HIDD / 64, BATCH / 64), 256>>>(x, W1, H, HIDD, INDIM,
                                                    b1, gam, bet, mean, var);
    // 2) A = x @ Wa^T                          [512,512]
    gemm64<1><<<dim3(HIDD / 64, BATCH / 64), 256>>>(x, Wa, A, HIDD, INDIM,
                                                    nullptr, nullptr, nullptr, nullptr, nullptr);
    // 3) C = x @ Wb^T + bs1                    [512,512]
    gemm64<2><<<dim3(HIDD / 64, BATCH / 64), 256>>>(x, Wb, C, HIDD, INDIM,
                                                    bs1, nullptr, nullptr, nullptr, nullptr);
    // 4) H2 = relu(H @ W2^T + b2)              [512,256]
    gemm64<3><<<dim3(HID2 / 64, BATCH / 64), 256>>>(H, W2, H2, HID2, HIDD,
                                                    b2, nullptr, nullptr, nullptr, nullptr);
    // 5) scores + softmax
    scores_kernel<<<BATCH / 4, 128>>>(H2, W3, b3, out_probs, out_scores);
    // 6) pairwise similarities
    sim_kernel<<<dim3(BATCH / 32, BATCH / 32), 256>>>(A, C, ws2, bs2, out_sim);
}

// round 2
// speedup vs baseline: 1.7834x; 1.7834x over previous
#include <cuda_runtime.h>
#include <math.h>

#define BATCH 512
#define INDIM 256
#define HIDD  512
#define HID2  256
#define PAT   10

typedef unsigned long long u64;

// -------- scratch (no allocations allowed) --------
__device__ float g_H [BATCH * HIDD];
__device__ float g_H2[BATCH * HID2];
__device__ float g_A [BATCH * HIDD];
__device__ float g_C [BATCH * HIDD];

// ---------- packed f32x2 helpers (sm_103a) ----------
__device__ __forceinline__ u64 pack2(float lo, float hi) {
    u64 r; asm("mov.b64 %0, {%1, %2};" : "=l"(r) : "f"(lo), "f"(hi)); return r;
}
__device__ __forceinline__ void unpack2(u64 v, float& lo, float& hi) {
    asm("mov.b64 {%0, %1}, %2;" : "=f"(lo), "=f"(hi) : "l"(v));
}
__device__ __forceinline__ u64 ffma2(u64 a, u64 b, u64 c) {
    u64 d; asm("fma.rn.f32x2 %0, %1, %2, %3;" : "=l"(d) : "l"(a), "l"(b), "l"(c)); return d;
}

// ============================================================
// GEMM tile: Out[m][n] = sum_k X[m][k]*W[n][k]  (+epilogue)
// 64m x 32n tile, 128 threads, 4x4 micro-tile, f32x2 FMA,
// double-buffered smem (1 barrier per 16-deep K chunk).
// smem layout (floats): Xs[2][16][64] at 0, Wt[2][16][32] at 2048.
// mode 0: BN(+b1)+ReLU ; 1: none ; 2: +p0 ; 3: relu(+p0)
// ============================================================
__device__ __forceinline__ void gemm_tile(
    const float* __restrict__ X, const float* __restrict__ W,
    float* __restrict__ Out, int N, int K, int m0, int n0, int mode,
    const float* __restrict__ p0, const float* __restrict__ p1,
    const float* __restrict__ p2, const float* __restrict__ p3,
    const float* __restrict__ p4, float* sm)
{
    float* Xs = sm;          // 2 * 16 * 64
    float* Wt = sm + 2048;   // 2 * 16 * 32

    const int t   = threadIdx.x;
    const int txn = t & 7;        // n quad (4 cols)
    const int tym = t >> 3;       // m quad (4 rows), 0..15

    const int xrow = t & 63;      // X loader row
    const int xkq  = t >> 6;      // 0..1 (handles kq and kq+2)
    const int wrow = t & 31;      // W loader row
    const int wkq  = t >> 5;      // 0..3

    const float* Xg = X + (size_t)(m0 + xrow) * K;
    const float* Wg = W + (size_t)(n0 + wrow) * K;

    // ---- load chunk 0 ----
    {
        float4 v0 = *(const float4*)(Xg + xkq * 4);
        float4 v1 = *(const float4*)(Xg + (xkq + 2) * 4);
        float4 wv = *(const float4*)(Wg + wkq * 4);
        Xs[(xkq*4+0)*64 + xrow] = v0.x; Xs[(xkq*4+1)*64 + xrow] = v0.y;
        Xs[(xkq*4+2)*64 + xrow] = v0.z; Xs[(xkq*4+3)*64 + xrow] = v0.w;
        Xs[((xkq+2)*4+0)*64 + xrow] = v1.x; Xs[((xkq+2)*4+1)*64 + xrow] = v1.y;
        Xs[((xkq+2)*4+2)*64 + xrow] = v1.z; Xs[((xkq+2)*4+3)*64 + xrow] = v1.w;
        Wt[(wkq*4+0)*32 + wrow] = wv.x; Wt[(wkq*4+1)*32 + wrow] = wv.y;
        Wt[(wkq*4+2)*32 + wrow] = wv.z; Wt[(wkq*4+3)*32 + wrow] = wv.w;
    }
    __syncthreads();

    u64 acc[4][2];
#pragma unroll
    for (int r = 0; r < 4; r++) { acc[r][0] = pack2(0.f, 0.f); acc[r][1] = acc[r][0]; }

    const int NC = K >> 4;
    for (int c = 0; c < NC; ++c) {
        const float* Xb = Xs + (c & 1) * 1024;
        const float* Wb = Wt + (c & 1) * 512;

        float4 v0, v1, wv;
        const bool pf = (c + 1 < NC);
        if (pf) {
            const int k0 = (c + 1) << 4;
            v0 = *(const float4*)(Xg + k0 + xkq * 4);
            v1 = *(const float4*)(Xg + k0 + (xkq + 2) * 4);
            wv = *(const float4*)(Wg + k0 + wkq * 4);
        }

#pragma unroll
        for (int kk = 0; kk < 16; kk++) {
            float4 a = *(const float4*)&Xb[kk * 64 + tym * 4];
            ulonglong2 b = *(const ulonglong2*)&Wb[kk * 32 + txn * 4];
            u64 a0 = pack2(a.x, a.x), a1 = pack2(a.y, a.y);
            u64 a2 = pack2(a.z, a.z), a3 = pack2(a.w, a.w);
            acc[0][0] = ffma2(a0, b.x, acc[0][0]); acc[0][1] = ffma2(a0, b.y, acc[0][1]);
            acc[1][0] = ffma2(a1, b.x, acc[1][0]); acc[1][1] = ffma2(a1, b.y, acc[1][1]);
            acc[2][0] = ffma2(a2, b.x, acc[2][0]); acc[2][1] = ffma2(a2, b.y, acc[2][1]);
            acc[3][0] = ffma2(a3, b.x, acc[3][0]); acc[3][1] = ffma2(a3, b.y, acc[3][1]);
        }

        if (pf) {
            float* Xn = Xs + ((c + 1) & 1) * 1024;
            float* Wn = Wt + ((c + 1) & 1) * 512;
            Xn[(xkq*4+0)*64 + xrow] = v0.x; Xn[(xkq*4+1)*64 + xrow] = v0.y;
            Xn[(xkq*4+2)*64 + xrow] = v0.z; Xn[(xkq*4+3)*64 + xrow] = v0.w;
            Xn[((xkq+2)*4+0)*64 + xrow] = v1.x; Xn[((xkq+2)*4+1)*64 + xrow] = v1.y;
            Xn[((xkq+2)*4+2)*64 + xrow] = v1.z; Xn[((xkq+2)*4+3)*64 + xrow] = v1.w;
            Wn[(wkq*4+0)*32 + wrow] = wv.x; Wn[(wkq*4+1)*32 + wrow] = wv.y;
            Wn[(wkq*4+2)*32 + wrow] = wv.z; Wn[(wkq*4+3)*32 + wrow] = wv.w;
        }
        __syncthreads();
    }

    // ---- epilogue ----
    const int n = n0 + txn * 4;
    float4 q0 = make_float4(0.f, 0.f, 0.f, 0.f), q1 = q0, q2 = q0, q3 = q0, q4 = q0;
    if (mode == 0) {
        q0 = *(const float4*)(p0 + n); q1 = *(const float4*)(p1 + n);
        q2 = *(const float4*)(p2 + n); q3 = *(const float4*)(p3 + n);
        q4 = *(const float4*)(p4 + n);
    } else if (mode == 2 || mode == 3) {
        q0 = *(const float4*)(p0 + n);
    }
    const float* bias = &q0.x;
    const float* gam  = &q1.x;
    const float* bet  = &q2.x;
    const float* mean = &q3.x;
    const float* var  = &q4.x;

#pragma unroll
    for (int r = 0; r < 4; r++) {
        float v[4];
        unpack2(acc[r][0], v[0], v[1]);
        unpack2(acc[r][1], v[2], v[3]);
#pragma unroll
        for (int c2 = 0; c2 < 4; c2++) {
            float v2 = v[c2];
            if (mode == 0) {
                v2 += bias[c2];
                v2 = gam[c2] * (v2 - mean[c2]) * rsqrtf(var[c2] + 1e-5f) + bet[c2];
                v2 = fmaxf(v2, 0.f);
            } else if (mode == 2) {
                v2 += bias[c2];
            } else if (mode == 3) {
                v2 = fmaxf(v2 + bias[c2], 0.f);
            }
            v[c2] = v2;
        }
        *(float4*)(Out + (size_t)(m0 + tym * 4 + r) * N + n) =
            make_float4(v[0], v[1], v[2], v[3]);
    }
}

// ============================================================
// Launch 1: three fused x-projections (H via BN+ReLU, A, C+bs1)
// grid (16 n-tiles, 8 m-tiles, 3 weights), 128 threads.
// ============================================================
__global__ __launch_bounds__(128)
void k_proj(const float* __restrict__ x,
            const float* __restrict__ W1, const float* __restrict__ b1,
            const float* __restrict__ gam, const float* __restrict__ bet,
            const float* __restrict__ mean, const float* __restrict__ var,
            const float* __restrict__ Wa, const float* __restrict__ Wb,
            const float* __restrict__ bs1)
{
    __shared__ __align__(16) float sm[3072];
    const int m0 = blockIdx.y * 64;
    const int n0 = blockIdx.x * 32;
    const int z  = blockIdx.z;
    if (z == 0)
        gemm_tile(x, W1, g_H, HIDD, INDIM, m0, n0, 0, b1, gam, bet, mean, var, sm);
    else if (z == 1)
        gemm_tile(x, Wa, g_A, HIDD, INDIM, m0, n0, 1,
                  nullptr, nullptr, nullptr, nullptr, nullptr, sm);
    else
        gemm_tile(x, Wb, g_C, HIDD, INDIM, m0, n0, 2,
                  bs1, nullptr, nullptr, nullptr, nullptr, sm);
}

// ============================================================
// Launch 2: blocks [0,136) = pairwise-similarity tiles (upper tri),
//           blocks [136,200) = H2 = relu(H @ W2^T + b2).
// 128 threads per block.
// sim: 32x32 pair tile, 2(i) x 4(j) micro-tile, K=512 in 32-chunks,
//      double-buffered. logit = sum_k relu(A[i,k]+C[j,k])*w[k] + bs2.
// ============================================================
__global__ __launch_bounds__(128)
void k_simh2(const float* __restrict__ W2, const float* __restrict__ b2,
             const float* __restrict__ ws2, const float* __restrict__ bs2p,
             float* __restrict__ out_sim)
{
    __shared__ __align__(16) float sm[4160];

    if (blockIdx.x >= 136) {
        const int idx = blockIdx.x - 136;          // 0..63
        const int m0 = (idx >> 3) * 64;            // 8 m-tiles
        const int n0 = (idx & 7) * 32;             // 8 n-tiles
        gemm_tile(g_H, W2, g_H2, HID2, HIDD, m0, n0, 3,
                  b2, nullptr, nullptr, nullptr, nullptr, sm);
        return;
    }

    // ---- similarity tile ----
    float* As = sm;          // 2 * 32 * 32
    float* Cs = sm + 2048;   // 2 * 32 * 32
    float* Ws = sm + 4096;   // 2 * 32

    // decode upper-triangle tile (bi <= bj) from linear block id
    int rb = blockIdx.x, bi = 0;
    while (rb >= 16 - bi) { rb -= 16 - bi; ++bi; }
    const int bj = bi + rb;
    const int i0 = bi * 32, j0 = bj * 32;

    const int t  = threadIdx.x;
    const int tx = t & 7;     // j quad (4 cols)
    const int ty = t >> 3;    // i pair (2 rows), 0..15

    const int lrow = t & 31;  // loader row
    const int lkq  = t >> 5;  // 0..3 (handles kq and kq+4)

    const float* Ag = g_A + (size_t)(i0 + lrow) * HIDD;
    const float* Cg = g_C + (size_t)(j0 + lrow) * HIDD;

    // ---- load chunk 0 ----
    {
        float4 a0 = *(const float4*)(Ag + lkq * 4);
        float4 a1 = *(const float4*)(Ag + (lkq + 4) * 4);
        float4 c0 = *(const float4*)(Cg + lkq * 4);
        float4 c1 = *(const float4*)(Cg + (lkq + 4) * 4);
        As[(lkq*4+0)*32 + lrow] = a0.x; As[(lkq*4+1)*32 + lrow] = a0.y;
        As[(lkq*4+2)*32 + lrow] = a0.z; As[(lkq*4+3)*32 + lrow] = a0.w;
        As[((lkq+4)*4+0)*32 + lrow] = a1.x; As[((lkq+4)*4+1)*32 + lrow] = a1.y;
        As[((lkq+4)*4+2)*32 + lrow] = a1.z; As[((lkq+4)*4+3)*32 + lrow] = a1.w;
        Cs[(lkq*4+0)*32 + lrow] = c0.x; Cs[(lkq*4+1)*32 + lrow] = c0.y;
        Cs[(lkq*4+2)*32 + lrow] = c0.z; Cs[(lkq*4+3)*32 + lrow] = c0.w;
        Cs[((lkq+4)*4+0)*32 + lrow] = c1.x; Cs[((lkq+4)*4+1)*32 + lrow] = c1.y;
        Cs[((lkq+4)*4+2)*32 + lrow] = c1.z; Cs[((lkq+4)*4+3)*32 + lrow] = c1.w;
        if (t < 8) *(float4*)&Ws[t * 4] = *(const float4*)(ws2 + t * 4);
    }
    __syncthreads();

    float acc[2][4];
#pragma unroll
    for (int r = 0; r < 2; r++)
#pragma unroll
        for (int c = 0; c < 4; c++) acc[r][c] = 0.f;

    for (int ch = 0; ch < 16; ++ch) {
        const float* Ab = As + (ch & 1) * 1024;
        const float* Cb = Cs + (ch & 1) * 1024;
        const float* Wb = Ws + (ch & 1) * 32;

        float4 a0, a1, c0, c1, wv;
        const bool pf = (ch + 1 < 16);
        if (pf) {
            const int k0 = (ch + 1) << 5;
            a0 = *(const float4*)(Ag + k0 + lkq * 4);
            a1 = *(const float4*)(Ag + k0 + (lkq + 4) * 4);
            c0 = *(const float4*)(Cg + k0 + lkq * 4);
            c1 = *(const float4*)(Cg + k0 + (lkq + 4) * 4);
            if (t < 8) wv = *(const float4*)(ws2 + k0 + t * 4);
        }

#pragma unroll
        for (int kk = 0; kk < 32; kk++) {
            float2 a = *(const float2*)&Ab[kk * 32 + ty * 2];
            float4 cc = *(const float4*)&Cb[kk * 32 + tx * 4];
            const float w = Wb[kk];
            acc[0][0] += fmaxf(a.x + cc.x, 0.f) * w;
            acc[0][1] += fmaxf(a.x + cc.y, 0.f) * w;
            acc[0][2] += fmaxf(a.x + cc.z, 0.f) * w;
            acc[0][3] += fmaxf(a.x + cc.w, 0.f) * w;
            acc[1][0] += fmaxf(a.y + cc.x, 0.f) * w;
            acc[1][1] += fmaxf(a.y + cc.y, 0.f) * w;
            acc[1][2] += fmaxf(a.y + cc.z, 0.f) * w;
            acc[1][3] += fmaxf(a.y + cc.w, 0.f) * w;
        }

        if (pf) {
            float* An = As + ((ch + 1) & 1) * 1024;
            float* Cn = Cs + ((ch + 1) & 1) * 1024;
            An[(lkq*4+0)*32 + lrow] = a0.x; An[(lkq*4+1)*32 + lrow] = a0.y;
            An[(lkq*4+2)*32 + lrow] = a0.z; An[(lkq*4+3)*32 + lrow] = a0.w;
            An[((lkq+4)*4+0)*32 + lrow] = a1.x; An[((lkq+4)*4+1)*32 + lrow] = a1.y;
            An[((lkq+4)*4+2)*32 + lrow] = a1.z; An[((lkq+4)*4+3)*32 + lrow] = a1.w;
            Cn[(lkq*4+0)*32 + lrow] = c0.x; Cn[(lkq*4+1)*32 + lrow] = c0.y;
            Cn[(lkq*4+2)*32 + lrow] = c0.z; Cn[(lkq*4+3)*32 + lrow] = c0.w;
            Cn[((lkq+4)*4+0)*32 + lrow] = c1.x; Cn[((lkq+4)*4+1)*32 + lrow] = c1.y;
            Cn[((lkq+4)*4+2)*32 + lrow] = c1.z; Cn[((lkq+4)*4+3)*32 + lrow] = c1.w;
            if (t < 8) *(float4*)&Ws[((ch + 1) & 1) * 32 + t * 4] = wv;
        }
        __syncthreads();
    }

    const float bs2 = *bs2p;
#pragma unroll
    for (int r = 0; r < 2; r++) {
#pragma unroll
        for (int c = 0; c < 4; c++) {
            const int i = i0 + ty * 2 + r;
            const int j = j0 + tx * 4 + c;
            if (i < j) {
                const float s = 1.f / (1.f + __expf(-(acc[r][c] + bs2)));
                out_sim[(size_t)i * BATCH + j] = s;
                out_sim[(size_t)j * BATCH + i] = s;
            } else if (i == j) {
                out_sim[(size_t)i * BATCH + j] = 0.f;
            }
        }
    }
}

// ============================================================
// Launch 3: scores + softmax (reads g_H2), one warp per row.
// ============================================================
__global__ __launch_bounds__(128)
void k_scores(const float* __restrict__ W3, const float* __restrict__ b3,
              float* __restrict__ out_probs, float* __restrict__ out_scores)
{
    const int warp = threadIdx.x >> 5;
    const int lane = threadIdx.x & 31;
    const int row  = blockIdx.x * 4 + warp;
    const float* h = g_H2 + (size_t)row * HID2;

    float acc[PAT];
#pragma unroll
    for (int p = 0; p < PAT; p++) acc[p] = 0.f;

    for (int k = lane; k < HID2; k += 32) {
        const float hv = h[k];
#pragma unroll
        for (int p = 0; p < PAT; p++) acc[p] += hv * W3[p * HID2 + k];
    }
#pragma unroll
    for (int p = 0; p < PAT; p++) {
#pragma unroll
        for (int off = 16; off; off >>= 1)
            acc[p] += __shfl_xor_sync(0xFFFFFFFFu, acc[p], off);
    }
    if (lane == 0) {
        float s[PAT], e[PAT];
        float mx = -1e30f;
#pragma unroll
        for (int p = 0; p < PAT; p++) { s[p] = acc[p] + b3[p]; mx = fmaxf(mx, s[p]); }
        float sum = 0.f;
#pragma unroll
        for (int p = 0; p < PAT; p++) { e[p] = __expf(s[p] - mx); sum += e[p]; }
        const float inv = 1.f / sum;
#pragma unroll
        for (int p = 0; p < PAT; p++) {
            out_scores[row * PAT + p] = s[p];
            out_probs [row * PAT + p] = e[p] * inv;
        }
    }
}

// ============================================================
extern "C" void kernel_launch(void* const* d_in, const int* in_sizes, int n_in,
                              void* d_out, int out_size)
{
    const float* x    = (const float*)d_in[0];
    const float* W1   = (const float*)d_in[1];
    const float* b1   = (const float*)d_in[2];
    const float* gam  = (const float*)d_in[3];
    const float* bet  = (const float*)d_in[4];
    const float* mean = (const float*)d_in[5];
    const float* var  = (const float*)d_in[6];
    const float* W2   = (const float*)d_in[7];
    const float* b2   = (const float*)d_in[8];
    const float* W3   = (const float*)d_in[9];
    const float* b3   = (const float*)d_in[10];
    const float* Wa   = (const float*)d_in[11];
    const float* Wb   = (const float*)d_in[12];
    const float* bs1  = (const float*)d_in[13];
    const float* ws2  = (const float*)d_in[14];
    const float* bs2  = (const float*)d_in[15];

    float* out        = (float*)d_out;
    float* out_probs  = out;
    float* out_scores = out + BATCH * PAT;
    float* out_sim    = out + 2 * BATCH * PAT;

    // 1) H, A, C projections (384 CTAs)
    k_proj<<<dim3(16, 8, 3), 128>>>(x, W1, b1, gam, bet, mean, var, Wa, Wb, bs1);
    // 2) sim (136 CTAs) + H2 (64 CTAs) concurrently in one launch
    k_simh2<<<200, 128>>>(W2, b2, ws2, bs2, out_sim);
    // 3) scores + softmax
    k_scores<<<BATCH / 4, 128>>>(W3, b3, out_probs, out_scores);
}